// round 1
// baseline (speedup 1.0000x reference)
#include <cuda_runtime.h>
#include <cstdint>

// HighOrderActivation: B=1024, G=512, K=4 (ARITY), D=64.
// out[b,g,:] = sum_k coef[k] * params[g, idx[k], :]
// where coef = (min, gaps of sorted X[b,g,:]) and idx is the reversed cumsum
// of 2^argsort. Since argsort is a permutation of {0,1,2,3}:
//   idx[0] = 15, idx[1] = 15 - 2^i0, idx[2] = 2^i2 + 2^i3, idx[3] = 2^i3.
//
// Layout: 16 threads per (b,g) pair; each thread computes one float4 of the
// 64-float output row. Writes are fully coalesced (256B per pair, contiguous
// across pairs). params (512*16*64 f32 = 2 MB) is L2-resident. Kernel is
// DRAM-write bound (~134 MB out).

#define BATCH   1024
#define GROUPS  512
#define OUT_D4  16          // 64 floats = 16 float4 per (b,g)
#define PAIRS   (BATCH * GROUPS)

__global__ __launch_bounds__(256, 8)
void hoa_kernel(const float4* __restrict__ Xv,      // [PAIRS] float4 (K=4 floats)
                const float4* __restrict__ Pv,      // [GROUPS*16*16] float4
                float4* __restrict__ Ov)            // [PAIRS*16] float4
{
    const int t  = blockIdx.x * 256 + threadIdx.x;
    const int p  = t >> 4;          // pair index = b*GROUPS + g
    const int d4 = t & 15;          // which float4 of the output row

    const int g = p & (GROUPS - 1); // GROUPS = 512 is a power of 2

    // Load the 4 input values for this pair (one LDG.128, broadcast across
    // the 16 lanes sharing the pair).
    const float4 x = Xv[p];

    float v0 = x.x, v1 = x.y, v2 = x.z, v3 = x.w;
    int   i0 = 0,   i1 = 1,   i2 = 2,   i3 = 3;

    // 5-comparator sorting network for 4 elements, tracking original indices.
    #define CSWAP(a, b, ia, ib)                           \
        { if (a > b) { float _tv = a; a = b; b = _tv;     \
                       int _ti = ia; ia = ib; ib = _ti; } }
    CSWAP(v0, v1, i0, i1);
    CSWAP(v2, v3, i2, i3);
    CSWAP(v0, v2, i0, i2);
    CSWAP(v1, v3, i1, i3);
    CSWAP(v1, v2, i1, i2);
    #undef CSWAP

    // Barycentric-style coefficients: smallest, then successive gaps.
    const float c0 = v0;
    const float c1 = v1 - v0;
    const float c2 = v2 - v1;
    const float c3 = v3 - v2;

    // Vertex indices (reversed cumsum of 2^argsort).
    const int e0 = 1 << i0;
    const int e2 = 1 << i2;
    const int e3 = 1 << i3;
    const int id1 = 15 - e0;
    const int id2 = e2 + e3;
    const int id3 = e3;

    // params[g] is a [16, 64] f32 table = [16, 16] float4.
    const float4* __restrict__ base = Pv + (size_t)g * (16 * OUT_D4);

    const float4 p0 = base[15  * OUT_D4 + d4];
    const float4 p1 = base[id1 * OUT_D4 + d4];
    const float4 p2 = base[id2 * OUT_D4 + d4];
    const float4 p3 = base[id3 * OUT_D4 + d4];

    float4 o;
    o.x = c0 * p0.x + c1 * p1.x + c2 * p2.x + c3 * p3.x;
    o.y = c0 * p0.y + c1 * p1.y + c2 * p2.y + c3 * p3.y;
    o.z = c0 * p0.z + c1 * p1.z + c2 * p2.z + c3 * p3.z;
    o.w = c0 * p0.w + c1 * p1.w + c2 * p2.w + c3 * p3.w;

    Ov[(size_t)p * OUT_D4 + d4] = o;
}

extern "C" void kernel_launch(void* const* d_in, const int* in_sizes, int n_in,
                              void* d_out, int out_size)
{
    const float4* Xv = (const float4*)d_in[0];   // X: [1024, 512, 4] f32
    const float4* Pv = (const float4*)d_in[1];   // params: [512, 16, 64] f32
    float4*       Ov = (float4*)d_out;           // out: [1024, 512, 64] f32

    // PAIRS * 16 threads total = 8,388,608; 256 threads/block -> 32768 blocks.
    const int total_threads = PAIRS * OUT_D4;
    const int block = 256;
    const int grid  = total_threads / block;     // exact division

    hoa_kernel<<<grid, block>>>(Xv, Pv, Ov);
}

// round 3
// speedup vs baseline: 1.1928x; 1.1928x over previous
#include <cuda_runtime.h>
#include <cstdint>

// HighOrderActivation: B=1024, G=512, K=4, D=64.
// out[b,g,:] = c0*P[g,15,:] + c1*P[g,15-2^i0,:] + c2*P[g,2^i2+2^i3,:] + c3*P[g,2^i3,:]
// where (i0..i3) = argsort(X[b,g,:]) and c = (min, successive gaps).
//
// R1 change: 8 threads per (b,g) pair (was 16). Each thread computes two
// float4 chunks (q and q+8) of the 64-float output row. Halves the per-pair
// issue cost of the redundant sort while keeping every LDG/STG a full,
// aligned 128B line (8 lanes x 16B).

#define BATCH   1024
#define GROUPS  512
#define PAIRS   (BATCH * GROUPS)

__global__ __launch_bounds__(256, 8)
void hoa_kernel(const float4* __restrict__ Xv,      // [PAIRS] float4
                const float4* __restrict__ Pv,      // [GROUPS*16*16] float4
                float4* __restrict__ Ov)            // [PAIRS*16] float4
{
    const int t = blockIdx.x * 256 + threadIdx.x;
    const int p = t >> 3;           // pair index = b*GROUPS + g
    const int q = t & 7;            // float4 chunk within first half-row

    const int g = p & (GROUPS - 1); // GROUPS = 512 (power of 2)

    // One 16B broadcast load per pair (8 lanes share it).
    const float4 x = Xv[p];

    float v0 = x.x, v1 = x.y, v2 = x.z, v3 = x.w;
    int   i0 = 0,   i1 = 1,   i2 = 2,   i3 = 3;

    // 5-comparator sorting network, FMNMX for values + SEL for indices.
    #define CSWAP(a, b, ia, ib)                         \
        { bool _sw = (a > b);                           \
          float _lo = fminf(a, b), _hi = fmaxf(a, b);   \
          a = _lo; b = _hi;                             \
          int _t = ia; ia = _sw ? ib : ia; ib = _sw ? _t : ib; }
    CSWAP(v0, v1, i0, i1);
    CSWAP(v2, v3, i2, i3);
    CSWAP(v0, v2, i0, i2);
    CSWAP(v1, v3, i1, i3);
    CSWAP(v1, v2, i1, i2);
    #undef CSWAP

    const float c0 = v0;
    const float c1 = v1 - v0;
    const float c2 = v2 - v1;
    const float c3 = v3 - v2;

    const int e0 = 1 << i0;
    const int e2 = 1 << i2;
    const int e3 = 1 << i3;
    const int id1 = 15 - e0;
    const int id2 = e2 + e3;
    const int id3 = e3;

    // params[g]: [16 rows, 16 float4]. Row r chunk c at base + r*16 + c.
    const float4* __restrict__ base = Pv + g * 256;

    const float4* r0 = base + 15  * 16 + q;
    const float4* r1 = base + id1 * 16 + q;
    const float4* r2 = base + id2 * 16 + q;
    const float4* r3 = base + id3 * 16 + q;

    // Chunk A (float4 q) and chunk B (float4 q+8): full 128B lines per warp.
    const float4 a0 = r0[0], b0 = r0[8];
    const float4 a1 = r1[0], b1 = r1[8];
    const float4 a2 = r2[0], b2 = r2[8];
    const float4 a3 = r3[0], b3 = r3[8];

    float4 oa, ob;
    oa.x = c0 * a0.x + c1 * a1.x + c2 * a2.x + c3 * a3.x;
    oa.y = c0 * a0.y + c1 * a1.y + c2 * a2.y + c3 * a3.y;
    oa.z = c0 * a0.z + c1 * a1.z + c2 * a2.z + c3 * a3.z;
    oa.w = c0 * a0.w + c1 * a1.w + c2 * a2.w + c3 * a3.w;

    ob.x = c0 * b0.x + c1 * b1.x + c2 * b2.x + c3 * b3.x;
    ob.y = c0 * b0.y + c1 * b1.y + c2 * b2.y + c3 * b3.y;
    ob.z = c0 * b0.z + c1 * b1.z + c2 * b2.z + c3 * b3.z;
    ob.w = c0 * b0.w + c1 * b1.w + c2 * b2.w + c3 * b3.w;

    float4* __restrict__ o = Ov + p * 16 + q;
    o[0] = oa;
    o[8] = ob;
}

extern "C" void kernel_launch(void* const* d_in, const int* in_sizes, int n_in,
                              void* d_out, int out_size)
{
    const float4* Xv = (const float4*)d_in[0];   // X: [1024, 512, 4] f32
    const float4* Pv = (const float4*)d_in[1];   // params: [512, 16, 64] f32
    float4*       Ov = (float4*)d_out;           // out: [1024, 512, 64] f32

    const int total_threads = PAIRS * 8;         // 4,194,304
    const int block = 256;
    const int grid  = total_threads / block;     // 16384

    hoa_kernel<<<grid, block>>>(Xv, Pv, Ov);
}

// round 4
// speedup vs baseline: 1.2518x; 1.0495x over previous
#include <cuda_runtime.h>
#include <cstdint>

// HighOrderActivation: B=1024, G=512, K=4, D=64.
// out[b,g,:] = c0*P[g,15,:] + c1*P[g,15-2^i0,:] + c2*P[g,2^i2+2^i3,:] + c3*P[g,2^i3,:]
// (i0..i3) = argsort(X[b,g,:]); c = (min, successive gaps of sorted values).
//
// R3 change: one block = one g, 32 consecutive b (8 lanes per pair).
// Row-15 gathers become warp-uniform (1 wavefront instead of 4), and the
// data-dependent rows (id1 in {7,11,13,14}, id3 in {1,2,4,8}, id2 in 6 values)
// get probabilistic line-sharing among the 4 pairs of a warp. Cuts L1TEX
// gather wavefronts ~40%, which is the measured bottleneck (L1=74.6%).

#define BATCH   1024
#define GROUPS  512
#define B_TILE  32          // pairs (b values) per block
#define PAIRS   (BATCH * GROUPS)

__global__ __launch_bounds__(256, 8)
void hoa_kernel(const float4* __restrict__ Xv,      // [PAIRS] float4
                const float4* __restrict__ Pv,      // [GROUPS*16*16] float4
                float4* __restrict__ Ov)            // [PAIRS*16] float4
{
    const int tid = threadIdx.x;
    const int g   = blockIdx.x & (GROUPS - 1);      // block-uniform group
    const int b   = ((blockIdx.x >> 9) << 5) + (tid >> 3);
    const int q   = tid & 7;                         // float4 chunk 0..7

    const int p = b * GROUPS + g;                    // pair index

    // 16B broadcast load per pair (8 lanes share it).
    const float4 x = Xv[p];

    float v0 = x.x, v1 = x.y, v2 = x.z, v3 = x.w;
    int   i0 = 0,   i1 = 1,   i2 = 2,   i3 = 3;

    // 5-comparator sorting network, FMNMX + SEL.
    #define CSWAP(a, bb, ia, ib)                        \
        { bool _sw = (a > bb);                          \
          float _lo = fminf(a, bb), _hi = fmaxf(a, bb); \
          a = _lo; bb = _hi;                            \
          int _t = ia; ia = _sw ? ib : ia; ib = _sw ? _t : ib; }
    CSWAP(v0, v1, i0, i1);
    CSWAP(v2, v3, i2, i3);
    CSWAP(v0, v2, i0, i2);
    CSWAP(v1, v3, i1, i3);
    CSWAP(v1, v2, i1, i2);
    #undef CSWAP

    const float c0 = v0;
    const float c1 = v1 - v0;
    const float c2 = v2 - v1;
    const float c3 = v3 - v2;

    const int e0 = 1 << i0;
    const int e2 = 1 << i2;
    const int e3 = 1 << i3;
    const int id1 = 15 - e0;
    const int id2 = e2 + e3;
    const int id3 = e3;

    // params[g]: [16 rows, 16 float4]; block-uniform base.
    const float4* __restrict__ base = Pv + g * 256;

    const float4* r0 = base + 15  * 16 + q;   // warp-uniform line (broadcast)
    const float4* r1 = base + id1 * 16 + q;
    const float4* r2 = base + id2 * 16 + q;
    const float4* r3 = base + id3 * 16 + q;

    const float4 a0 = r0[0], b0 = r0[8];
    const float4 a1 = r1[0], b1 = r1[8];
    const float4 a2 = r2[0], b2 = r2[8];
    const float4 a3 = r3[0], b3 = r3[8];

    float4 oa, ob;
    oa.x = c0 * a0.x + c1 * a1.x + c2 * a2.x + c3 * a3.x;
    oa.y = c0 * a0.y + c1 * a1.y + c2 * a2.y + c3 * a3.y;
    oa.z = c0 * a0.z + c1 * a1.z + c2 * a2.z + c3 * a3.z;
    oa.w = c0 * a0.w + c1 * a1.w + c2 * a2.w + c3 * a3.w;

    ob.x = c0 * b0.x + c1 * b1.x + c2 * b2.x + c3 * b3.x;
    ob.y = c0 * b0.y + c1 * b1.y + c2 * b2.y + c3 * b3.y;
    ob.z = c0 * b0.z + c1 * b1.z + c2 * b2.z + c3 * b3.z;
    ob.w = c0 * b0.w + c1 * b1.w + c2 * b2.w + c3 * b3.w;

    float4* __restrict__ o = Ov + (size_t)p * 16 + q;
    o[0] = oa;
    o[8] = ob;
}

extern "C" void kernel_launch(void* const* d_in, const int* in_sizes, int n_in,
                              void* d_out, int out_size)
{
    const float4* Xv = (const float4*)d_in[0];   // X: [1024, 512, 4] f32
    const float4* Pv = (const float4*)d_in[1];   // params: [512, 16, 64] f32
    float4*       Ov = (float4*)d_out;           // out: [1024, 512, 64] f32

    // One block per (g, 32-b tile): 512 * 32 = 16384 blocks, 256 thr each.
    const int grid = GROUPS * (BATCH / B_TILE);
    hoa_kernel<<<grid, 256>>>(Xv, Pv, Ov);
}